// round 1
// baseline (speedup 1.0000x reference)
#include <cuda_runtime.h>
#include <math.h>

// Problem constants (fixed shapes)
#define NROWS 8192
#define DDIM  128
#define BM    64
#define BN    128
#define PAD   132          // row pitch in floats (16B-aligned, bank-friendly)
#define NTHREADS 256
#define ALPHA 2.0f

__device__ double g_supcon;
__device__ double g_pt;

__global__ void esup_zero_kernel() {
    g_supcon = 0.0;
    g_pt = 0.0;
}

__global__ __launch_bounds__(NTHREADS, 1)
void esup_main_kernel(const float* __restrict__ z_au,
                      const float* __restrict__ z_tp,
                      const float* __restrict__ fc) {
    extern __shared__ float smem[];
    float* sAau = smem;                    // [BM][PAD]
    float* sAtp = sAau + BM * PAD;         // [BM][PAD]
    float* sBau = sAtp + BM * PAD;         // [BN][PAD]
    float* sBtp = sBau + BN * PAD;         // [BN][PAD]

    const int tid = threadIdx.x;
    const int tx = tid & 15;               // 0..15  -> column group
    const int ty = tid >> 4;               // 0..15  -> row group
    const int i0 = blockIdx.x * BM;

    // ---- Load A tiles (this CTA's 64 rows of z_au / z_tp), once ----
    {
        const int colq = tid & 31;         // float4 index along D
        const int row0 = tid >> 5;         // 0..7
        #pragma unroll
        for (int it = 0; it < BM / 8; ++it) {
            int row = row0 + it * 8;
            const float4 va = *(const float4*)(z_au + (size_t)(i0 + row) * DDIM + colq * 4);
            const float4 vt = *(const float4*)(z_tp + (size_t)(i0 + row) * DDIM + colq * 4);
            *(float4*)(sAau + row * PAD + colq * 4) = va;
            *(float4*)(sAtp + row * PAD + colq * 4) = vt;
        }
    }

    // Per-thread online logsumexp state for its 4 rows (row = ty + 16*r)
    float mpos[4], lpos[4], mneg[4], lneg[4];
    #pragma unroll
    for (int r = 0; r < 4; ++r) {
        mpos[r] = -1e30f; lpos[r] = 0.0f;
        mneg[r] = -1e30f; lneg[r] = 0.0f;
    }

    // ---- Stream over column tiles ----
    for (int jt = 0; jt < NROWS / BN; ++jt) {
        const int j0 = jt * BN;
        __syncthreads();   // previous tile's compute done before overwriting B
        {
            const int colq = tid & 31;
            const int row0 = tid >> 5;
            #pragma unroll
            for (int it = 0; it < BN / 8; ++it) {
                int row = row0 + it * 8;
                const float4 va = *(const float4*)(z_au + (size_t)(j0 + row) * DDIM + colq * 4);
                const float4 vt = *(const float4*)(z_tp + (size_t)(j0 + row) * DDIM + colq * 4);
                *(float4*)(sBau + row * PAD + colq * 4) = va;
                *(float4*)(sBtp + row * PAD + colq * 4) = vt;
            }
        }
        __syncthreads();

        // ---- 4x8 micro-tile, 3 similarity matrices ----
        float aa[4][8], tt[4][8], at[4][8];
        #pragma unroll
        for (int r = 0; r < 4; ++r)
            #pragma unroll
            for (int c = 0; c < 8; ++c) { aa[r][c] = 0.f; tt[r][c] = 0.f; at[r][c] = 0.f; }

        for (int k = 0; k < DDIM; k += 4) {
            float4 a_au[4], a_tp[4];
            #pragma unroll
            for (int r = 0; r < 4; ++r) {
                a_au[r] = *(const float4*)(sAau + (ty + 16 * r) * PAD + k);
                a_tp[r] = *(const float4*)(sAtp + (ty + 16 * r) * PAD + k);
            }
            #pragma unroll
            for (int c = 0; c < 8; ++c) {
                const float4 b_au = *(const float4*)(sBau + (tx + 16 * c) * PAD + k);
                const float4 b_tp = *(const float4*)(sBtp + (tx + 16 * c) * PAD + k);
                #pragma unroll
                for (int r = 0; r < 4; ++r) {
                    aa[r][c] += a_au[r].x * b_au.x; aa[r][c] += a_au[r].y * b_au.y;
                    aa[r][c] += a_au[r].z * b_au.z; aa[r][c] += a_au[r].w * b_au.w;
                    tt[r][c] += a_tp[r].x * b_tp.x; tt[r][c] += a_tp[r].y * b_tp.y;
                    tt[r][c] += a_tp[r].z * b_tp.z; tt[r][c] += a_tp[r].w * b_tp.w;
                    at[r][c] += a_au[r].x * b_tp.x; at[r][c] += a_au[r].y * b_tp.y;
                    at[r][c] += a_au[r].z * b_tp.z; at[r][c] += a_au[r].w * b_tp.w;
                }
            }
        }

        // ---- Online logsumexp update with diagonal masking ----
        #pragma unroll
        for (int r = 0; r < 4; ++r) {
            const int gi = i0 + ty + 16 * r;
            float va[8], vt[8], vn[8];
            float vmaxp = -1e30f, vmaxn = -1e30f;
            #pragma unroll
            for (int c = 0; c < 8; ++c) {
                const int gj = j0 + tx + 16 * c;
                const bool dm = (gj == gi);
                va[c] = dm ? -1e30f : aa[r][c];
                vt[c] = dm ? -1e30f : tt[r][c];
                vn[c] = dm ? -1e30f : at[r][c];
                vmaxp = fmaxf(vmaxp, fmaxf(va[c], vt[c]));
                vmaxn = fmaxf(vmaxn, vn[c]);
            }
            // pos stream (aa + tt combined)
            float nm = fmaxf(mpos[r], vmaxp);
            float s = lpos[r] * __expf(mpos[r] - nm);
            #pragma unroll
            for (int c = 0; c < 8; ++c) s += __expf(va[c] - nm) + __expf(vt[c] - nm);
            lpos[r] = s; mpos[r] = nm;
            // neg stream (at)
            nm = fmaxf(mneg[r], vmaxn);
            s = lneg[r] * __expf(mneg[r] - nm);
            #pragma unroll
            for (int c = 0; c < 8; ++c) s += __expf(vn[c] - nm);
            lneg[r] = s; mneg[r] = nm;
        }
    }

    __syncthreads();

    // ---- Stash per-thread stats into SMEM (reuse B region) ----
    float* sStat = sBau;                   // [64][16][4] = 4096 floats
    #pragma unroll
    for (int r = 0; r < 4; ++r) {
        const int row = ty + 16 * r;
        float* p = sStat + (row * 16 + tx) * 4;
        p[0] = mpos[r]; p[1] = lpos[r]; p[2] = mneg[r]; p[3] = lneg[r];
    }

    // ---- Diagonal (au_i . tp_i) and prototype partials (reuse sBtp) ----
    float* sDiag = sBtp;                   // [64][4]
    float* sPt   = sBtp + 256;             // [64][4]
    {
        const int row = tid & 63;
        const int part = tid >> 6;         // 0..3
        const int kb = part * 32;
        float dsum = 0.f, psum = 0.f;
        #pragma unroll 8
        for (int kk = 0; kk < 32; ++kk) {
            const int k = kb + kk;
            const float a = sAau[row * PAD + k];
            const float b = sAtp[row * PAD + k];
            const float w = fc[DDIM + k] - fc[k];   // pt1 - pt0
            dsum += a * b;
            psum += (a - b) * w;
        }
        sDiag[row * 4 + part] = dsum;
        sPt[row * 4 + part]   = psum;
    }
    __syncthreads();

    float* sRow = sBtp + 512;              // [64]
    float* sPtr = sBtp + 576;              // [64]
    if (tid < 64) {
        const int row = tid;
        float M = -1e30f, L = 0.f, Mn = -1e30f, Ln = 0.f;
        for (int t = 0; t < 16; ++t) {
            const float* p = sStat + (row * 16 + t) * 4;
            float m = p[0], l = p[1];
            if (m > M) { L = L * __expf(M - m) + l; M = m; }
            else       { L += l * __expf(m - M); }
            m = p[2]; l = p[3];
            if (m > Mn) { Ln = Ln * __expf(Mn - m) + l; Mn = m; }
            else        { Ln += l * __expf(m - Mn); }
        }
        const float pos = M + logf(L);
        const float neg = Mn + logf(Ln);
        const float diag = sDiag[row * 4 + 0] + sDiag[row * 4 + 1] +
                           sDiag[row * 4 + 2] + sDiag[row * 4 + 3];
        const float pt   = sPt[row * 4 + 0] + sPt[row * 4 + 1] +
                           sPt[row * 4 + 2] + sPt[row * 4 + 3];
        sRow[row] = -pos + neg + ALPHA * diag;
        sPtr[row] = pt;
    }
    __syncthreads();

    if (tid == 0) {
        double s = 0.0, p = 0.0;
        for (int i = 0; i < 64; ++i) { s += (double)sRow[i]; p += (double)sPtr[i]; }
        atomicAdd(&g_supcon, s);
        atomicAdd(&g_pt, p);
    }
}

__global__ void esup_finalize_kernel(float* out) {
    out[0] = (float)((g_pt / (double)NROWS + g_supcon) / (double)(NROWS + 2));
}

extern "C" void kernel_launch(void* const* d_in, const int* in_sizes, int n_in,
                              void* d_out, int out_size) {
    const float* z_au = (const float*)d_in[0];
    const float* z_tp = (const float*)d_in[1];
    const float* fc   = (const float*)d_in[2];
    // d_in[3] = labels (int64) — unused by the math.
    float* out = (float*)d_out;

    const size_t smembytes = (size_t)(2 * BM * PAD + 2 * BN * PAD) * sizeof(float); // 202752
    cudaFuncSetAttribute(esup_main_kernel,
                         cudaFuncAttributeMaxDynamicSharedMemorySize, (int)smembytes);

    esup_zero_kernel<<<1, 1>>>();
    esup_main_kernel<<<NROWS / BM, NTHREADS, smembytes>>>(z_au, z_tp, fc);
    esup_finalize_kernel<<<1, 1>>>(out);
}